// round 2
// baseline (speedup 1.0000x reference)
#include <cuda_runtime.h>
#include <math.h>

// Problem constants
#define B 8
#define N 2048
#define PTS (B * N)        // 16384
#define KNN 16
#define DM 128             // d_model
#define DP 64              // d_points
#define RES_ELEMS (PTS * DP)

// ----------------------------------------------------------------------------
// Scratch (device globals; no runtime allocation allowed)
// ----------------------------------------------------------------------------
__device__ float g_x[PTS * DM];
__device__ float g_q[PTS * DM];
__device__ float g_k[PTS * DM];
__device__ float g_v[PTS * DM];
__device__ int   g_knn[PTS * KNN];

// ----------------------------------------------------------------------------
// Kernel 1: KNN.  One block = 128 rows of one batch; one thread per row.
// Reproduces reference: dists = sq_i + sq_j - 2*dot, stable argsort,
// take indices [0:32:2].  Non-FMA arithmetic to match reference rounding;
// ties broken by smaller index (stable sort semantics).
// ----------------------------------------------------------------------------
__global__ __launch_bounds__(128) void knn_kernel(const float* __restrict__ xyz) {
    __shared__ float s_x[N], s_y[N], s_z[N], s_sq[N];
    const int b = blockIdx.y;
    const int tid = threadIdx.x;
    const float* X = xyz + (size_t)b * N * 3;

    for (int i = tid; i < N; i += 128) {
        float x = X[i * 3 + 0], y = X[i * 3 + 1], z = X[i * 3 + 2];
        s_x[i] = x; s_y[i] = y; s_z[i] = z;
        s_sq[i] = __fadd_rn(__fadd_rn(__fmul_rn(x, x), __fmul_rn(y, y)), __fmul_rn(z, z));
    }
    __syncthreads();

    const int r = blockIdx.x * 128 + tid;
    const float px = s_x[r], py = s_y[r], pz = s_z[r], psq = s_sq[r];

    float bd[32];
    int   bi[32];
#pragma unroll
    for (int i = 0; i < 32; i++) { bd[i] = 3.4e38f; bi[i] = 0x7fffffff; }

    for (int j = 0; j < N; j++) {
        float dot = __fadd_rn(__fadd_rn(__fmul_rn(px, s_x[j]), __fmul_rn(py, s_y[j])),
                              __fmul_rn(pz, s_z[j]));
        float d = __fsub_rn(__fadd_rn(psq, s_sq[j]), __fmul_rn(2.0f, dot));
        if (d < bd[31] || (d == bd[31] && j < bi[31])) {
            int pos = 31;
            while (pos > 0 && (bd[pos - 1] > d || (bd[pos - 1] == d && bi[pos - 1] > j))) {
                bd[pos] = bd[pos - 1]; bi[pos] = bi[pos - 1]; pos--;
            }
            bd[pos] = d; bi[pos] = j;
        }
    }
#pragma unroll
    for (int t = 0; t < KNN; t++)
        g_knn[((size_t)b * N + r) * KNN + t] = bi[2 * t];
}

// ----------------------------------------------------------------------------
// Column-register GEMM: C[M x 128] = A[M x K] @ W[K x 128] (+bias).
// blockDim=128, each thread owns one output column (weight column in regs).
// 32 rows per block, processed in two 16-row smem chunks.
// ----------------------------------------------------------------------------
template <int K, bool BIAS, int DST>
__global__ __launch_bounds__(128, 2) void colgemm_kernel(const float* __restrict__ Ain,
                                                         const float* __restrict__ W,
                                                         const float* __restrict__ bias) {
    const int tid = threadIdx.x;
    // Select source / destination from device globals (DST: 0=x from param A,
    // 1=q, 2=k, 3=v reading g_x)
    const float* A = (DST == 0) ? Ain : g_x;
    float* C = (DST == 0) ? g_x : (DST == 1) ? g_q : (DST == 2) ? g_k : g_v;

    float w[K];
#pragma unroll
    for (int k = 0; k < K; k++) w[k] = W[k * DM + tid];
    const float bv = BIAS ? bias[tid] : 0.0f;

    __shared__ float s_a[16 * K];
    const int rowBase = blockIdx.x * 32;

    for (int c = 0; c < 2; c++) {
        const int rb = rowBase + c * 16;
        const float4* src = (const float4*)(A + (size_t)rb * K);
        float4* dst = (float4*)s_a;
        for (int i = tid; i < 16 * K / 4; i += 128) dst[i] = src[i];
        __syncthreads();
#pragma unroll
        for (int j = 0; j < 16; j++) {
            const float4* row = (const float4*)(s_a + j * K);
            float acc = bv;
#pragma unroll
            for (int k4 = 0; k4 < K / 4; k4++) {
                float4 a = row[k4];
                acc += a.x * w[4 * k4 + 0];
                acc += a.y * w[4 * k4 + 1];
                acc += a.z * w[4 * k4 + 2];
                acc += a.w * w[4 * k4 + 3];
            }
            C[(size_t)(rb + j) * DM + tid] = acc;
        }
        __syncthreads();
    }
}

// ----------------------------------------------------------------------------
// Kernel 3: fully fused per-point attention.
// One block per point (16384 blocks), 128 threads (one per channel).
//   pos_enc MLP -> h -> gamma MLP -> per-channel softmax over 16 neighbors
//   -> weighted sum -> fc2 + residual.  Writes attn and res to d_out.
// ----------------------------------------------------------------------------
__global__ __launch_bounds__(128, 2) void point_attn_kernel(
    const float* __restrict__ xyz, const float* __restrict__ feat,
    const float* __restrict__ Wd1, const float* __restrict__ bd1,
    const float* __restrict__ Wd2, const float* __restrict__ bd2,
    const float* __restrict__ Wg1, const float* __restrict__ bg1,
    const float* __restrict__ Wg2, const float* __restrict__ bg2,
    const float* __restrict__ W2, const float* __restrict__ b2,
    float* __restrict__ out_res, float* __restrict__ out_attn) {
    __shared__ float s_h1[16 * DM];   // delta-MLP hidden, then g1
    __shared__ float s_A[16 * DM];    // k gather, then h
    __shared__ float s_B[16 * DM];    // v gather, then v + pos_enc
    __shared__ float s_q[DM];
    __shared__ float s_res[DM];
    __shared__ int   s_knn[KNN];
    __shared__ float s_dx[KNN], s_dy[KNN], s_dz[KNN];

    const int p = blockIdx.x;
    const int base = (p >> 11) << 11;  // batch row base (b*2048)
    const int tid = threadIdx.x;

    if (tid < KNN) {
        int nb = g_knn[(size_t)p * KNN + tid];
        s_knn[tid] = nb;
        s_dx[tid] = xyz[(size_t)p * 3 + 0] - xyz[(size_t)(base + nb) * 3 + 0];
        s_dy[tid] = xyz[(size_t)p * 3 + 1] - xyz[(size_t)(base + nb) * 3 + 1];
        s_dz[tid] = xyz[(size_t)p * 3 + 2] - xyz[(size_t)(base + nb) * 3 + 2];
    }
    s_q[tid] = g_q[(size_t)p * DM + tid];
    __syncthreads();

    // Gathers (k, v) + delta-MLP first layer (K=3)
    {
        const float wd0 = Wd1[tid], wd1v = Wd1[DM + tid], wd2v = Wd1[2 * DM + tid];
        const float bb = bd1[tid];
#pragma unroll
        for (int j = 0; j < KNN; j++) {
            const size_t gr = (size_t)(base + s_knn[j]) * DM + tid;
            s_A[j * DM + tid] = g_k[gr];
            s_B[j * DM + tid] = g_v[gr];
            float h1 = s_dx[j] * wd0 + s_dy[j] * wd1v + s_dz[j] * wd2v + bb;
            s_h1[j * DM + tid] = fmaxf(h1, 0.0f);
        }
    }
    __syncthreads();

    // pos_enc = h1 @ Wd2 + bd2; fuse into h = q - k + pe and vpe = v + pe
    {
        float w[DM];
#pragma unroll
        for (int k = 0; k < DM; k++) w[k] = Wd2[k * DM + tid];
        const float bv = bd2[tid];
        const float qv = s_q[tid];
#pragma unroll
        for (int j = 0; j < KNN; j++) {
            const float4* row = (const float4*)(s_h1 + j * DM);
            float acc = bv;
#pragma unroll
            for (int k4 = 0; k4 < DM / 4; k4++) {
                float4 a = row[k4];
                acc += a.x * w[4 * k4 + 0];
                acc += a.y * w[4 * k4 + 1];
                acc += a.z * w[4 * k4 + 2];
                acc += a.w * w[4 * k4 + 3];
            }
            float kv = s_A[j * DM + tid];
            float vv = s_B[j * DM + tid];
            s_A[j * DM + tid] = qv - kv + acc;  // h
            s_B[j * DM + tid] = vv + acc;       // v + pos_enc
        }
    }
    __syncthreads();

    // g1 = relu(h @ Wg1 + bg1)  -> s_h1
    {
        float w[DM];
#pragma unroll
        for (int k = 0; k < DM; k++) w[k] = Wg1[k * DM + tid];
        const float bv = bg1[tid];
#pragma unroll
        for (int j = 0; j < KNN; j++) {
            const float4* row = (const float4*)(s_A + j * DM);
            float acc = bv;
#pragma unroll
            for (int k4 = 0; k4 < DM / 4; k4++) {
                float4 a = row[k4];
                acc += a.x * w[4 * k4 + 0];
                acc += a.y * w[4 * k4 + 1];
                acc += a.z * w[4 * k4 + 2];
                acc += a.w * w[4 * k4 + 3];
            }
            s_h1[j * DM + tid] = fmaxf(acc, 0.0f);
        }
    }
    __syncthreads();

    // logits = g1 @ Wg2 + bg2 (kept in registers), softmax over neighbors,
    // weighted sum of (v + pos_enc)
    float logit[KNN];
    {
        float w[DM];
#pragma unroll
        for (int k = 0; k < DM; k++) w[k] = Wg2[k * DM + tid];
        const float bv = bg2[tid];
#pragma unroll
        for (int j = 0; j < KNN; j++) {
            const float4* row = (const float4*)(s_h1 + j * DM);
            float acc = bv;
#pragma unroll
            for (int k4 = 0; k4 < DM / 4; k4++) {
                float4 a = row[k4];
                acc += a.x * w[4 * k4 + 0];
                acc += a.y * w[4 * k4 + 1];
                acc += a.z * w[4 * k4 + 2];
                acc += a.w * w[4 * k4 + 3];
            }
            logit[j] = acc;
        }
    }
    const float scale = 0.0883883476483184405501055452631f;  // 1/sqrt(128)
    float m = -3.4e38f;
#pragma unroll
    for (int j = 0; j < KNN; j++) m = fmaxf(m, logit[j] * scale);
    float e[KNN];
    float sum = 0.0f;
#pragma unroll
    for (int j = 0; j < KNN; j++) { e[j] = expf(logit[j] * scale - m); sum += e[j]; }

    float r = 0.0f;
#pragma unroll
    for (int j = 0; j < KNN; j++) {
        float a = e[j] / sum;
        out_attn[((size_t)p * KNN + j) * DM + tid] = a;
        r += a * s_B[j * DM + tid];
    }
    s_res[tid] = r;
    __syncthreads();

    // fc2 (128 -> 64) + residual (pre = features)
    if (tid < DP) {
        float acc = b2[tid];
        const float4* rr = (const float4*)s_res;
#pragma unroll
        for (int k4 = 0; k4 < DM / 4; k4++) {
            float4 a = rr[k4];
            acc += a.x * W2[(4 * k4 + 0) * DP + tid];
            acc += a.y * W2[(4 * k4 + 1) * DP + tid];
            acc += a.z * W2[(4 * k4 + 2) * DP + tid];
            acc += a.w * W2[(4 * k4 + 3) * DP + tid];
        }
        out_res[(size_t)p * DP + tid] = acc + feat[(size_t)p * DP + tid];
    }
}

// ----------------------------------------------------------------------------
// Launch
// Input order (setup_inputs dict order):
// 0 xyz, 1 features, 2 W1, 3 b1, 4 W2, 5 b2, 6 Wd1, 7 bd1, 8 Wd2, 9 bd2,
// 10 Wg1, 11 bg1, 12 Wg2, 13 bg2, 14 Wq, 15 Wk, 16 Wv
// Output: res (16384*64) followed by attn (16384*16*128), fp32.
// ----------------------------------------------------------------------------
extern "C" void kernel_launch(void* const* d_in, const int* in_sizes, int n_in,
                              void* d_out, int out_size) {
    const float* xyz  = (const float*)d_in[0];
    const float* feat = (const float*)d_in[1];
    const float* W1   = (const float*)d_in[2];
    const float* b1   = (const float*)d_in[3];
    const float* W2   = (const float*)d_in[4];
    const float* b2   = (const float*)d_in[5];
    const float* Wd1  = (const float*)d_in[6];
    const float* bd1  = (const float*)d_in[7];
    const float* Wd2  = (const float*)d_in[8];
    const float* bd2  = (const float*)d_in[9];
    const float* Wg1  = (const float*)d_in[10];
    const float* bg1  = (const float*)d_in[11];
    const float* Wg2  = (const float*)d_in[12];
    const float* bg2  = (const float*)d_in[13];
    const float* Wq   = (const float*)d_in[14];
    const float* Wk   = (const float*)d_in[15];
    const float* Wv   = (const float*)d_in[16];

    float* out_res  = (float*)d_out;
    float* out_attn = (float*)d_out + RES_ELEMS;

    // 1) KNN indices
    knn_kernel<<<dim3(16, B), 128>>>(xyz);

    // 2) x = features @ W1 + b1
    colgemm_kernel<64, true, 0><<<PTS / 32, 128>>>(feat, W1, b1);

    // 3) q/k/v = x @ {Wq, Wk, Wv}
    colgemm_kernel<128, false, 1><<<PTS / 32, 128>>>(nullptr, Wq, nullptr);
    colgemm_kernel<128, false, 2><<<PTS / 32, 128>>>(nullptr, Wk, nullptr);
    colgemm_kernel<128, false, 3><<<PTS / 32, 128>>>(nullptr, Wv, nullptr);

    // 4) fused pos-enc + gamma + softmax + weighted sum + fc2
    point_attn_kernel<<<PTS, 128>>>(xyz, feat, Wd1, bd1, Wd2, bd2,
                                    Wg1, bg1, Wg2, bg2, W2, b2,
                                    out_res, out_attn);
}

// round 3
// speedup vs baseline: 1.0839x; 1.0839x over previous
#include <cuda_runtime.h>
#include <math.h>

// Problem constants
#define B 8
#define N 2048
#define PTS (B * N)        // 16384
#define KNN 16
#define DM 128             // d_model
#define DP 64              // d_points
#define RES_ELEMS (PTS * DP)

// ----------------------------------------------------------------------------
// Scratch (device globals; no runtime allocation allowed)
// ----------------------------------------------------------------------------
__device__ float g_x[PTS * DM];
__device__ float g_q[PTS * DM];
__device__ float g_k[PTS * DM];
__device__ float g_v[PTS * DM];
__device__ int   g_knn[PTS * KNN];

// ----------------------------------------------------------------------------
// Kernel 1: KNN.  One block = 128 rows of one batch; one thread per row.
// Reproduces reference: dists = sq_i + sq_j - 2*dot, stable argsort,
// take indices [0:32:2].  Non-FMA arithmetic matches reference rounding;
// ties broken by smaller index (stable sort semantics).
// The current-worst (bd[31], bi[31]) is cached in registers so the hot
// no-insert path never touches the (local-memory) arrays.
// ----------------------------------------------------------------------------
__global__ __launch_bounds__(128) void knn_kernel(const float* __restrict__ xyz) {
    __shared__ float s_x[N], s_y[N], s_z[N], s_sq[N];
    const int b = blockIdx.y;
    const int tid = threadIdx.x;
    const float* X = xyz + (size_t)b * N * 3;

    for (int i = tid; i < N; i += 128) {
        float x = X[i * 3 + 0], y = X[i * 3 + 1], z = X[i * 3 + 2];
        s_x[i] = x; s_y[i] = y; s_z[i] = z;
        s_sq[i] = __fadd_rn(__fadd_rn(__fmul_rn(x, x), __fmul_rn(y, y)), __fmul_rn(z, z));
    }
    __syncthreads();

    const int r = blockIdx.x * 128 + tid;
    const float px = s_x[r], py = s_y[r], pz = s_z[r], psq = s_sq[r];

    float bd[32];
    int   bi[32];
#pragma unroll
    for (int i = 0; i < 32; i++) { bd[i] = 3.4e38f; bi[i] = 0x7fffffff; }
    float thr = 3.4e38f;          // == bd[31], register-cached
    int   thr_i = 0x7fffffff;     // == bi[31]

    for (int j = 0; j < N; j++) {
        float dot = __fadd_rn(__fadd_rn(__fmul_rn(px, s_x[j]), __fmul_rn(py, s_y[j])),
                              __fmul_rn(pz, s_z[j]));
        float d = __fsub_rn(__fadd_rn(psq, s_sq[j]), __fmul_rn(2.0f, dot));
        if (d < thr || (d == thr && j < thr_i)) {
            int pos = 31;
            while (pos > 0 && (bd[pos - 1] > d || (bd[pos - 1] == d && bi[pos - 1] > j))) {
                bd[pos] = bd[pos - 1]; bi[pos] = bi[pos - 1]; pos--;
            }
            bd[pos] = d; bi[pos] = j;
            thr = bd[31]; thr_i = bi[31];
        }
    }
#pragma unroll
    for (int t = 0; t < KNN; t++)
        g_knn[((size_t)b * N + r) * KNN + t] = bi[2 * t];
}

// ----------------------------------------------------------------------------
// Core building block: 16-row x 128-col GEMM slice.
// Each thread owns output column `tid`.  Weights are consumed in 4 chunks of
// 32 (only 32 weight regs live at a time -> no spills); 16 persistent
// accumulators give 16 independent FFMA chains.
// ----------------------------------------------------------------------------
__device__ __forceinline__ void gemm16_128(const float* s_src,
                                           const float* __restrict__ Wm,
                                           float bv, int tid, float* acc) {
#pragma unroll
    for (int j = 0; j < 16; j++) acc[j] = bv;
#pragma unroll 1
    for (int kc = 0; kc < 4; kc++) {
        float w[32];
#pragma unroll
        for (int kk = 0; kk < 32; kk++) w[kk] = Wm[(kc * 32 + kk) * DM + tid];
#pragma unroll
        for (int j = 0; j < 16; j++) {
            const float4* row = (const float4*)(s_src + j * DM + kc * 32);
#pragma unroll
            for (int k4 = 0; k4 < 8; k4++) {
                float4 a = row[k4];
                acc[j] += a.x * w[4 * k4 + 0];
                acc[j] += a.y * w[4 * k4 + 1];
                acc[j] += a.z * w[4 * k4 + 2];
                acc[j] += a.w * w[4 * k4 + 3];
            }
        }
    }
}

// ----------------------------------------------------------------------------
// Kernel 2: fc1.  C[16 x 128] = A[16 x 64] @ W1 + b1.  16 rows per block.
// ----------------------------------------------------------------------------
__global__ __launch_bounds__(128, 4) void fc1_kernel(const float* __restrict__ A,
                                                     const float* __restrict__ W,
                                                     const float* __restrict__ bias) {
    const int tid = threadIdx.x;
    __shared__ float s_a[16 * 64];
    const int rb = blockIdx.x * 16;

    const float4* src = (const float4*)(A + (size_t)rb * 64);
    float4* dst = (float4*)s_a;
    for (int i = tid; i < 16 * 64 / 4; i += 128) dst[i] = src[i];
    __syncthreads();

    float acc[16];
    const float bv = bias[tid];
#pragma unroll
    for (int j = 0; j < 16; j++) acc[j] = bv;
#pragma unroll 1
    for (int kc = 0; kc < 2; kc++) {
        float w[32];
#pragma unroll
        for (int kk = 0; kk < 32; kk++) w[kk] = W[(kc * 32 + kk) * DM + tid];
#pragma unroll
        for (int j = 0; j < 16; j++) {
            const float4* row = (const float4*)(s_a + j * 64 + kc * 32);
#pragma unroll
            for (int k4 = 0; k4 < 8; k4++) {
                float4 a = row[k4];
                acc[j] += a.x * w[4 * k4 + 0];
                acc[j] += a.y * w[4 * k4 + 1];
                acc[j] += a.z * w[4 * k4 + 2];
                acc[j] += a.w * w[4 * k4 + 3];
            }
        }
    }
#pragma unroll
    for (int j = 0; j < 16; j++) g_x[(size_t)(rb + j) * DM + tid] = acc[j];
}

// ----------------------------------------------------------------------------
// Kernel 3: q/k/v projections fused.  Stage 16 rows of x once, apply 3 weights.
// ----------------------------------------------------------------------------
__global__ __launch_bounds__(128, 4) void qkv_kernel(const float* __restrict__ Wq,
                                                     const float* __restrict__ Wk,
                                                     const float* __restrict__ Wv) {
    const int tid = threadIdx.x;
    __shared__ float s_a[16 * DM];
    const int rb = blockIdx.x * 16;

    const float4* src = (const float4*)(g_x + (size_t)rb * DM);
    float4* dst = (float4*)s_a;
    for (int i = tid; i < 16 * DM / 4; i += 128) dst[i] = src[i];
    __syncthreads();

    float acc[16];
    gemm16_128(s_a, Wq, 0.0f, tid, acc);
#pragma unroll
    for (int j = 0; j < 16; j++) g_q[(size_t)(rb + j) * DM + tid] = acc[j];
    gemm16_128(s_a, Wk, 0.0f, tid, acc);
#pragma unroll
    for (int j = 0; j < 16; j++) g_k[(size_t)(rb + j) * DM + tid] = acc[j];
    gemm16_128(s_a, Wv, 0.0f, tid, acc);
#pragma unroll
    for (int j = 0; j < 16; j++) g_v[(size_t)(rb + j) * DM + tid] = acc[j];
}

// ----------------------------------------------------------------------------
// Kernel 4: fully fused per-point attention.
// One block per point (16384 blocks), 128 threads (one per channel).
// ----------------------------------------------------------------------------
__global__ __launch_bounds__(128, 3) void point_attn_kernel(
    const float* __restrict__ xyz, const float* __restrict__ feat,
    const float* __restrict__ Wd1, const float* __restrict__ bd1,
    const float* __restrict__ Wd2, const float* __restrict__ bd2,
    const float* __restrict__ Wg1, const float* __restrict__ bg1,
    const float* __restrict__ Wg2, const float* __restrict__ bg2,
    const float* __restrict__ W2, const float* __restrict__ b2,
    float* __restrict__ out_res, float* __restrict__ out_attn) {
    __shared__ float s_h1[16 * DM];   // delta-MLP hidden, then g1
    __shared__ float s_A[16 * DM];    // k gather, then h
    __shared__ float s_B[16 * DM];    // v gather, then v + pos_enc
    __shared__ float s_q[DM];
    __shared__ float s_res[DM];
    __shared__ int   s_knn[KNN];
    __shared__ float s_dx[KNN], s_dy[KNN], s_dz[KNN];

    const int p = blockIdx.x;
    const int base = (p >> 11) << 11;  // batch row base (b*2048)
    const int tid = threadIdx.x;

    if (tid < KNN) {
        int nb = g_knn[(size_t)p * KNN + tid];
        s_knn[tid] = nb;
        s_dx[tid] = xyz[(size_t)p * 3 + 0] - xyz[(size_t)(base + nb) * 3 + 0];
        s_dy[tid] = xyz[(size_t)p * 3 + 1] - xyz[(size_t)(base + nb) * 3 + 1];
        s_dz[tid] = xyz[(size_t)p * 3 + 2] - xyz[(size_t)(base + nb) * 3 + 2];
    }
    s_q[tid] = g_q[(size_t)p * DM + tid];
    __syncthreads();

    // Gathers (k, v) + delta-MLP first layer (K=3)
    {
        const float wd0 = Wd1[tid], wd1v = Wd1[DM + tid], wd2v = Wd1[2 * DM + tid];
        const float bb = bd1[tid];
#pragma unroll
        for (int j = 0; j < KNN; j++) {
            const size_t gr = (size_t)(base + s_knn[j]) * DM + tid;
            s_A[j * DM + tid] = g_k[gr];
            s_B[j * DM + tid] = g_v[gr];
            float h1 = s_dx[j] * wd0 + s_dy[j] * wd1v + s_dz[j] * wd2v + bb;
            s_h1[j * DM + tid] = fmaxf(h1, 0.0f);
        }
    }
    __syncthreads();

    float acc[16];

    // pos_enc = h1 @ Wd2 + bd2; fuse into h = q - k + pe and vpe = v + pe.
    // Each thread touches only its own column of s_A/s_B -> no cross-thread
    // hazard before the next __syncthreads.
    gemm16_128(s_h1, Wd2, bd2[tid], tid, acc);
    {
        const float qv = s_q[tid];
#pragma unroll
        for (int j = 0; j < KNN; j++) {
            float kv = s_A[j * DM + tid];
            float vv = s_B[j * DM + tid];
            s_A[j * DM + tid] = qv - kv + acc[j];  // h
            s_B[j * DM + tid] = vv + acc[j];       // v + pos_enc
        }
    }
    __syncthreads();

    // g1 = relu(h @ Wg1 + bg1) -> s_h1
    gemm16_128(s_A, Wg1, bg1[tid], tid, acc);
#pragma unroll
    for (int j = 0; j < KNN; j++) s_h1[j * DM + tid] = fmaxf(acc[j], 0.0f);
    __syncthreads();

    // logits = g1 @ Wg2 + bg2 (in regs), softmax over neighbors, weighted sum
    gemm16_128(s_h1, Wg2, bg2[tid], tid, acc);

    const float scale = 0.0883883476483184405501055452631f;  // 1/sqrt(128)
    float m = -3.4e38f;
#pragma unroll
    for (int j = 0; j < KNN; j++) m = fmaxf(m, acc[j] * scale);
    float e[KNN];
    float sum = 0.0f;
#pragma unroll
    for (int j = 0; j < KNN; j++) { e[j] = expf(acc[j] * scale - m); sum += e[j]; }

    float r = 0.0f;
    const float inv = 1.0f / sum;
#pragma unroll
    for (int j = 0; j < KNN; j++) {
        float a = e[j] * inv;
        out_attn[((size_t)p * KNN + j) * DM + tid] = a;
        r += a * s_B[j * DM + tid];
    }
    s_res[tid] = r;
    __syncthreads();

    // fc2 (128 -> 64) + residual (pre = features)
    if (tid < DP) {
        float accr = b2[tid];
        const float4* rr = (const float4*)s_res;
#pragma unroll
        for (int k4 = 0; k4 < DM / 4; k4++) {
            float4 a = rr[k4];
            accr += a.x * W2[(4 * k4 + 0) * DP + tid];
            accr += a.y * W2[(4 * k4 + 1) * DP + tid];
            accr += a.z * W2[(4 * k4 + 2) * DP + tid];
            accr += a.w * W2[(4 * k4 + 3) * DP + tid];
        }
        out_res[(size_t)p * DP + tid] = accr + feat[(size_t)p * DP + tid];
    }
}

// ----------------------------------------------------------------------------
// Launch
// Input order (setup_inputs dict order):
// 0 xyz, 1 features, 2 W1, 3 b1, 4 W2, 5 b2, 6 Wd1, 7 bd1, 8 Wd2, 9 bd2,
// 10 Wg1, 11 bg1, 12 Wg2, 13 bg2, 14 Wq, 15 Wk, 16 Wv
// Output: res (16384*64) followed by attn (16384*16*128), fp32.
// ----------------------------------------------------------------------------
extern "C" void kernel_launch(void* const* d_in, const int* in_sizes, int n_in,
                              void* d_out, int out_size) {
    const float* xyz  = (const float*)d_in[0];
    const float* feat = (const float*)d_in[1];
    const float* W1   = (const float*)d_in[2];
    const float* b1   = (const float*)d_in[3];
    const float* W2   = (const float*)d_in[4];
    const float* b2   = (const float*)d_in[5];
    const float* Wd1  = (const float*)d_in[6];
    const float* bd1  = (const float*)d_in[7];
    const float* Wd2  = (const float*)d_in[8];
    const float* bd2  = (const float*)d_in[9];
    const float* Wg1  = (const float*)d_in[10];
    const float* bg1  = (const float*)d_in[11];
    const float* Wg2  = (const float*)d_in[12];
    const float* bg2  = (const float*)d_in[13];
    const float* Wq   = (const float*)d_in[14];
    const float* Wk   = (const float*)d_in[15];
    const float* Wv   = (const float*)d_in[16];

    float* out_res  = (float*)d_out;
    float* out_attn = (float*)d_out + RES_ELEMS;

    // 1) KNN indices
    knn_kernel<<<dim3(16, B), 128>>>(xyz);

    // 2) x = features @ W1 + b1
    fc1_kernel<<<PTS / 16, 128>>>(feat, W1, b1);

    // 3) q/k/v = x @ {Wq, Wk, Wv}  (fused)
    qkv_kernel<<<PTS / 16, 128>>>(Wq, Wk, Wv);

    // 4) fused pos-enc + gamma + softmax + weighted sum + fc2
    point_attn_kernel<<<PTS, 128>>>(xyz, feat, Wd1, bd1, Wd2, bd2,
                                    Wg1, bg1, Wg2, bg2, W2, b2,
                                    out_res, out_attn);
}

// round 4
// speedup vs baseline: 6.3066x; 5.8186x over previous
#include <cuda_runtime.h>
#include <math.h>

// Problem constants
#define B 8
#define N 2048
#define PTS (B * N)        // 16384
#define KNN 16
#define DM 128             // d_model
#define DP 64              // d_points
#define RES_ELEMS (PTS * DP)

// ----------------------------------------------------------------------------
// Scratch (device globals; no runtime allocation allowed)
// ----------------------------------------------------------------------------
__device__ float g_x[PTS * DM];
__device__ float g_q[PTS * DM];
__device__ float g_k[PTS * DM];
__device__ float g_v[PTS * DM];
__device__ int   g_knn[PTS * KNN];

// ----------------------------------------------------------------------------
// Kernel 1: KNN.  One block = 128 rows of one batch; one thread per row.
// Reproduces reference: dists = sq_i + sq_j - 2*dot, stable argsort,
// take indices [0:32:2].  Non-FMA arithmetic matches reference rounding.
//
// Top-32 kept as SORTED u64 keys in REGISTERS:
//   key = (monotone_bits(d) << 32) | j
// so u64 '<' == lexicographic (d, j) == stable argsort order.
// Insertion is a fully unrolled, branch-free select network (no local mem,
// no divergent while-loop -> inserting lanes run in SIMD).
// ----------------------------------------------------------------------------
__global__ __launch_bounds__(128) void knn_kernel(const float* __restrict__ xyz) {
    __shared__ float4 s_p[N];  // (x, y, z, sq) per point: 32 KB
    const int b = blockIdx.y;
    const int tid = threadIdx.x;
    const float* X = xyz + (size_t)b * N * 3;

    for (int i = tid; i < N; i += 128) {
        float x = X[i * 3 + 0], y = X[i * 3 + 1], z = X[i * 3 + 2];
        float sq = __fadd_rn(__fadd_rn(__fmul_rn(x, x), __fmul_rn(y, y)), __fmul_rn(z, z));
        s_p[i] = make_float4(x, y, z, sq);
    }
    __syncthreads();

    const int r = blockIdx.x * 128 + tid;
    const float4 me = s_p[r];

    unsigned long long key[32];
#pragma unroll
    for (int i = 0; i < 32; i++) key[i] = 0xFFFFFFFFFFFFFFFFULL;

    for (int j = 0; j < N; j++) {
        const float4 c = s_p[j];
        float dot = __fadd_rn(__fadd_rn(__fmul_rn(me.x, c.x), __fmul_rn(me.y, c.y)),
                              __fmul_rn(me.z, c.z));
        float d = __fsub_rn(__fadd_rn(me.w, c.w), __fmul_rn(2.0f, dot));
        // Order-preserving float -> uint transform (handles negatives exactly)
        unsigned int u = __float_as_uint(d);
        u ^= ((unsigned int)((int)u >> 31)) | 0x80000000u;
        unsigned long long kkey = ((unsigned long long)u << 32) | (unsigned int)j;

        if (kkey < key[31]) {
            // Branch-free sorted insert: shift down everything > kkey, place kkey.
            // c_prev entering slot i == (kkey < old key[i]); starts true for i=31.
            bool c_prev = true;
#pragma unroll
            for (int i = 31; i > 0; i--) {
                bool c = kkey < key[i - 1];
                key[i] = c ? key[i - 1] : (c_prev ? kkey : key[i]);
                c_prev = c;
            }
            key[0] = c_prev ? kkey : key[0];
        }
    }
#pragma unroll
    for (int t = 0; t < KNN; t++)
        g_knn[((size_t)b * N + r) * KNN + t] = (int)(unsigned int)(key[2 * t] & 0xFFFFFFFFULL);
}

// ----------------------------------------------------------------------------
// Core building block: 16-row x 128-col GEMM slice.
// Each thread owns output column `tid`.  Weights are consumed in 4 chunks of
// 32 (only 32 weight regs live at a time -> no spills); 16 persistent
// accumulators give 16 independent FFMA chains.
// ----------------------------------------------------------------------------
__device__ __forceinline__ void gemm16_128(const float* s_src,
                                           const float* __restrict__ Wm,
                                           float bv, int tid, float* acc) {
#pragma unroll
    for (int j = 0; j < 16; j++) acc[j] = bv;
#pragma unroll 1
    for (int kc = 0; kc < 4; kc++) {
        float w[32];
#pragma unroll
        for (int kk = 0; kk < 32; kk++) w[kk] = Wm[(kc * 32 + kk) * DM + tid];
#pragma unroll
        for (int j = 0; j < 16; j++) {
            const float4* row = (const float4*)(s_src + j * DM + kc * 32);
#pragma unroll
            for (int k4 = 0; k4 < 8; k4++) {
                float4 a = row[k4];
                acc[j] += a.x * w[4 * k4 + 0];
                acc[j] += a.y * w[4 * k4 + 1];
                acc[j] += a.z * w[4 * k4 + 2];
                acc[j] += a.w * w[4 * k4 + 3];
            }
        }
    }
}

// ----------------------------------------------------------------------------
// Kernel 2: fc1.  C[16 x 128] = A[16 x 64] @ W1 + b1.  16 rows per block.
// ----------------------------------------------------------------------------
__global__ __launch_bounds__(128, 4) void fc1_kernel(const float* __restrict__ A,
                                                     const float* __restrict__ W,
                                                     const float* __restrict__ bias) {
    const int tid = threadIdx.x;
    __shared__ float s_a[16 * 64];
    const int rb = blockIdx.x * 16;

    const float4* src = (const float4*)(A + (size_t)rb * 64);
    float4* dst = (float4*)s_a;
    for (int i = tid; i < 16 * 64 / 4; i += 128) dst[i] = src[i];
    __syncthreads();

    float acc[16];
    const float bv = bias[tid];
#pragma unroll
    for (int j = 0; j < 16; j++) acc[j] = bv;
#pragma unroll 1
    for (int kc = 0; kc < 2; kc++) {
        float w[32];
#pragma unroll
        for (int kk = 0; kk < 32; kk++) w[kk] = W[(kc * 32 + kk) * DM + tid];
#pragma unroll
        for (int j = 0; j < 16; j++) {
            const float4* row = (const float4*)(s_a + j * 64 + kc * 32);
#pragma unroll
            for (int k4 = 0; k4 < 8; k4++) {
                float4 a = row[k4];
                acc[j] += a.x * w[4 * k4 + 0];
                acc[j] += a.y * w[4 * k4 + 1];
                acc[j] += a.z * w[4 * k4 + 2];
                acc[j] += a.w * w[4 * k4 + 3];
            }
        }
    }
#pragma unroll
    for (int j = 0; j < 16; j++) g_x[(size_t)(rb + j) * DM + tid] = acc[j];
}

// ----------------------------------------------------------------------------
// Kernel 3: q/k/v projections fused.  Stage 16 rows of x once, apply 3 weights.
// ----------------------------------------------------------------------------
__global__ __launch_bounds__(128, 4) void qkv_kernel(const float* __restrict__ Wq,
                                                     const float* __restrict__ Wk,
                                                     const float* __restrict__ Wv) {
    const int tid = threadIdx.x;
    __shared__ float s_a[16 * DM];
    const int rb = blockIdx.x * 16;

    const float4* src = (const float4*)(g_x + (size_t)rb * DM);
    float4* dst = (float4*)s_a;
    for (int i = tid; i < 16 * DM / 4; i += 128) dst[i] = src[i];
    __syncthreads();

    float acc[16];
    gemm16_128(s_a, Wq, 0.0f, tid, acc);
#pragma unroll
    for (int j = 0; j < 16; j++) g_q[(size_t)(rb + j) * DM + tid] = acc[j];
    gemm16_128(s_a, Wk, 0.0f, tid, acc);
#pragma unroll
    for (int j = 0; j < 16; j++) g_k[(size_t)(rb + j) * DM + tid] = acc[j];
    gemm16_128(s_a, Wv, 0.0f, tid, acc);
#pragma unroll
    for (int j = 0; j < 16; j++) g_v[(size_t)(rb + j) * DM + tid] = acc[j];
}

// ----------------------------------------------------------------------------
// Kernel 4: fully fused per-point attention.
// One block per point (16384 blocks), 128 threads (one per channel).
// ----------------------------------------------------------------------------
__global__ __launch_bounds__(128, 3) void point_attn_kernel(
    const float* __restrict__ xyz, const float* __restrict__ feat,
    const float* __restrict__ Wd1, const float* __restrict__ bd1,
    const float* __restrict__ Wd2, const float* __restrict__ bd2,
    const float* __restrict__ Wg1, const float* __restrict__ bg1,
    const float* __restrict__ Wg2, const float* __restrict__ bg2,
    const float* __restrict__ W2, const float* __restrict__ b2,
    float* __restrict__ out_res, float* __restrict__ out_attn) {
    __shared__ float s_h1[16 * DM];   // delta-MLP hidden, then g1
    __shared__ float s_A[16 * DM];    // k gather, then h
    __shared__ float s_B[16 * DM];    // v gather, then v + pos_enc
    __shared__ float s_q[DM];
    __shared__ float s_res[DM];
    __shared__ int   s_knn[KNN];
    __shared__ float s_dx[KNN], s_dy[KNN], s_dz[KNN];

    const int p = blockIdx.x;
    const int base = (p >> 11) << 11;  // batch row base (b*2048)
    const int tid = threadIdx.x;

    if (tid < KNN) {
        int nb = g_knn[(size_t)p * KNN + tid];
        s_knn[tid] = nb;
        s_dx[tid] = xyz[(size_t)p * 3 + 0] - xyz[(size_t)(base + nb) * 3 + 0];
        s_dy[tid] = xyz[(size_t)p * 3 + 1] - xyz[(size_t)(base + nb) * 3 + 1];
        s_dz[tid] = xyz[(size_t)p * 3 + 2] - xyz[(size_t)(base + nb) * 3 + 2];
    }
    s_q[tid] = g_q[(size_t)p * DM + tid];
    __syncthreads();

    // Gathers (k, v) + delta-MLP first layer (K=3)
    {
        const float wd0 = Wd1[tid], wd1v = Wd1[DM + tid], wd2v = Wd1[2 * DM + tid];
        const float bb = bd1[tid];
#pragma unroll
        for (int j = 0; j < KNN; j++) {
            const size_t gr = (size_t)(base + s_knn[j]) * DM + tid;
            s_A[j * DM + tid] = g_k[gr];
            s_B[j * DM + tid] = g_v[gr];
            float h1 = s_dx[j] * wd0 + s_dy[j] * wd1v + s_dz[j] * wd2v + bb;
            s_h1[j * DM + tid] = fmaxf(h1, 0.0f);
        }
    }
    __syncthreads();

    float acc[16];

    // pos_enc = h1 @ Wd2 + bd2; fuse into h = q - k + pe and vpe = v + pe.
    gemm16_128(s_h1, Wd2, bd2[tid], tid, acc);
    {
        const float qv = s_q[tid];
#pragma unroll
        for (int j = 0; j < KNN; j++) {
            float kv = s_A[j * DM + tid];
            float vv = s_B[j * DM + tid];
            s_A[j * DM + tid] = qv - kv + acc[j];  // h
            s_B[j * DM + tid] = vv + acc[j];       // v + pos_enc
        }
    }
    __syncthreads();

    // g1 = relu(h @ Wg1 + bg1) -> s_h1
    gemm16_128(s_A, Wg1, bg1[tid], tid, acc);
#pragma unroll
    for (int j = 0; j < KNN; j++) s_h1[j * DM + tid] = fmaxf(acc[j], 0.0f);
    __syncthreads();

    // logits = g1 @ Wg2 + bg2 (in regs), softmax over neighbors, weighted sum
    gemm16_128(s_h1, Wg2, bg2[tid], tid, acc);

    const float scale = 0.0883883476483184405501055452631f;  // 1/sqrt(128)
    float m = -3.4e38f;
#pragma unroll
    for (int j = 0; j < KNN; j++) m = fmaxf(m, acc[j] * scale);
    float e[KNN];
    float sum = 0.0f;
#pragma unroll
    for (int j = 0; j < KNN; j++) { e[j] = expf(acc[j] * scale - m); sum += e[j]; }

    float r = 0.0f;
    const float inv = 1.0f / sum;
#pragma unroll
    for (int j = 0; j < KNN; j++) {
        float a = e[j] * inv;
        out_attn[((size_t)p * KNN + j) * DM + tid] = a;
        r += a * s_B[j * DM + tid];
    }
    s_res[tid] = r;
    __syncthreads();

    // fc2 (128 -> 64) + residual (pre = features)
    if (tid < DP) {
        float accr = b2[tid];
        const float4* rr = (const float4*)s_res;
#pragma unroll
        for (int k4 = 0; k4 < DM / 4; k4++) {
            float4 a = rr[k4];
            accr += a.x * W2[(4 * k4 + 0) * DP + tid];
            accr += a.y * W2[(4 * k4 + 1) * DP + tid];
            accr += a.z * W2[(4 * k4 + 2) * DP + tid];
            accr += a.w * W2[(4 * k4 + 3) * DP + tid];
        }
        out_res[(size_t)p * DP + tid] = accr + feat[(size_t)p * DP + tid];
    }
}

// ----------------------------------------------------------------------------
// Launch
// Input order (setup_inputs dict order):
// 0 xyz, 1 features, 2 W1, 3 b1, 4 W2, 5 b2, 6 Wd1, 7 bd1, 8 Wd2, 9 bd2,
// 10 Wg1, 11 bg1, 12 Wg2, 13 bg2, 14 Wq, 15 Wk, 16 Wv
// Output: res (16384*64) followed by attn (16384*16*128), fp32.
// ----------------------------------------------------------------------------
extern "C" void kernel_launch(void* const* d_in, const int* in_sizes, int n_in,
                              void* d_out, int out_size) {
    const float* xyz  = (const float*)d_in[0];
    const float* feat = (const float*)d_in[1];
    const float* W1   = (const float*)d_in[2];
    const float* b1   = (const float*)d_in[3];
    const float* W2   = (const float*)d_in[4];
    const float* b2   = (const float*)d_in[5];
    const float* Wd1  = (const float*)d_in[6];
    const float* bd1  = (const float*)d_in[7];
    const float* Wd2  = (const float*)d_in[8];
    const float* bd2  = (const float*)d_in[9];
    const float* Wg1  = (const float*)d_in[10];
    const float* bg1  = (const float*)d_in[11];
    const float* Wg2  = (const float*)d_in[12];
    const float* bg2  = (const float*)d_in[13];
    const float* Wq   = (const float*)d_in[14];
    const float* Wk   = (const float*)d_in[15];
    const float* Wv   = (const float*)d_in[16];

    float* out_res  = (float*)d_out;
    float* out_attn = (float*)d_out + RES_ELEMS;

    // 1) KNN indices
    knn_kernel<<<dim3(16, B), 128>>>(xyz);

    // 2) x = features @ W1 + b1
    fc1_kernel<<<PTS / 16, 128>>>(feat, W1, b1);

    // 3) q/k/v = x @ {Wq, Wk, Wv}  (fused)
    qkv_kernel<<<PTS / 16, 128>>>(Wq, Wk, Wv);

    // 4) fused pos-enc + gamma + softmax + weighted sum + fc2
    point_attn_kernel<<<PTS, 128>>>(xyz, feat, Wd1, bd1, Wd2, bd2,
                                    Wg1, bg1, Wg2, bg2, W2, b2,
                                    out_res, out_attn);
}